// round 16
// baseline (speedup 1.0000x reference)
#include <cuda_runtime.h>
#include <cuda_bf16.h>
#include <math.h>

// ---------------- compile-time architecture dims ----------------
#define F_DIM 128
#define H_DIM 64
#define C_DIM 10
#define P_DIM 384           // 2*(F+H)
#define N_CAP 100000
#define R_CAP 16
#define G_CAP 1024
#define E_CAP 1000000
#define NBLK_B 512          // blocks for hist/scatter passes

// ---------------- scratch (static device arrays; no allocs) -----
__device__ float d_W[R_CAP * H_DIM * H_DIM];   // 256 KB  [r][k][n]
__device__ float d_y[(size_t)N_CAP * H_DIM];   // 25.6 MB  x @ w1_rel
__device__ float d_h[(size_t)N_CAP * H_DIM];   // 25.6 MB  node hidden
__device__ float d_o[(size_t)N_CAP * H_DIM];   // 25.6 MB  root-transform out
__device__ float d_o2[(size_t)N_CAP * H_DIM];  // 25.6 MB  rgcn message out
__device__ int   d_cnt[(size_t)N_CAP * R_CAP]; // 6.4 MB   per (node, rel) counts
__device__ float d_pool[(size_t)G_CAP * P_DIM];
__device__ int   d_offs[G_CAP + 1];
// relation bucketing (for k_rgcn3)
__device__ int2  d_bedge[E_CAP];               // (src, dst) sorted by relation
__device__ int   d_bhist[R_CAP * NBLK_B];
__device__ int   d_boff [R_CAP * NBLK_B];
__device__ int   d_bstart[R_CAP];
__device__ int   d_bcnt  [R_CAP];
// dst bucketing (for k_agg1b, atomic-free aggregation)
__device__ int2  d_dedge[E_CAP];               // (src, nrm_bits) sorted by dst
__device__ int   d_dcnt[N_CAP];
__device__ int   d_doff[N_CAP + 1];
__device__ int   d_dcur[N_CAP];
// decoupled-lookback scan state
__device__ int   d_ticket;
__device__ unsigned long long d_state[256];    // (flag<<32)|value; 1=agg, 2=prefix

// ---------------- vector reductions (sm_90+) --------------------
__device__ __forceinline__ void red_add_v2(float* addr, float a, float b) {
    asm volatile("red.global.add.v2.f32 [%0], {%1, %2};"
                 :: "l"(addr), "f"(a), "f"(b) : "memory");
}

// ---------------- tf32 mma helpers ------------------------------
__device__ __forceinline__ unsigned f2tf32(float x) {
    unsigned r;
    asm("cvt.rna.tf32.f32 %0, %1;" : "=r"(r) : "f"(x));
    return r;
}
__device__ __forceinline__ void mma_tf32(float& c0, float& c1, float& c2, float& c3,
                                         unsigned a0, unsigned a1, unsigned a2, unsigned a3,
                                         unsigned b0, unsigned b1) {
    asm volatile("mma.sync.aligned.m16n8k8.row.col.f32.tf32.tf32.f32 "
                 "{%0,%1,%2,%3}, {%4,%5,%6,%7}, {%8,%9}, {%0,%1,%2,%3};"
                 : "+f"(c0), "+f"(c1), "+f"(c2), "+f"(c3)
                 : "r"(a0), "r"(a1), "r"(a2), "r"(a3), "r"(b0), "r"(b1));
}

// ---------------- k_prep: zero counts/state, W = comp @ bases ---
__global__ void k_prep(const float* __restrict__ comp, const float* __restrict__ bases,
                       int R, int NB, int N) {
    int tid = blockIdx.x * blockDim.x + threadIdx.x;
    int nth = gridDim.x * blockDim.x;
    int total_cnt = N * R;
    for (int i = tid; i < total_cnt; i += nth) d_cnt[i] = 0;
    for (int i = tid; i < N; i += nth) d_dcnt[i] = 0;
    if (tid < 256) d_state[tid] = 0ULL;
    if (tid == 0) d_ticket = 0;
    int wtot = R * H_DIM * H_DIM;
    for (int i = tid; i < wtot; i += nth) {
        int r = i >> 12;          // / 4096
        int ij = i & 4095;
        float acc = 0.f;
        for (int b = 0; b < NB; b++)
            acc += comp[r * NB + b] * bases[b * 4096 + ij];
        d_W[i] = acc;
    }
}

// ---------------- k_zero: clear o2 (on stream B) ----------------
__global__ void k_zero(int N) {
    size_t tid = blockIdx.x * blockDim.x + threadIdx.x;
    size_t nth = (size_t)gridDim.x * blockDim.x;
    size_t no = (size_t)N * H_DIM / 4;
    float4 z = make_float4(0.f, 0.f, 0.f, 0.f);
    for (size_t i = tid; i < no; i += nth)
        ((float4*)d_o2)[i] = z;
}

// ---------------- k_proj_mma: [y|h] = x @ [w_rel|w_root] (+b1) --
__global__ __launch_bounds__(512, 1) void k_proj_mma(
    const float* __restrict__ x, const float* __restrict__ w_rel,
    const float* __restrict__ w_root, const float* __restrict__ b1, int N) {
    extern __shared__ uint2 smp[];
    uint2* sPhi = smp;                   // [n 0..127][kt*4+tig], stride 68
    uint2* sPlo = smp + 128 * 68;
    for (int i = threadIdx.x; i < 128 * 64; i += 512) {
        int n = i >> 6, j = i & 63;      // j = kt*4 + tig
        int kt = j >> 2, tig = j & 3;
        int k1 = kt * 8 + tig, k2 = k1 + 4;
        float v1 = (n < 64) ? w_rel[k1 * 64 + n] : w_root[k1 * 64 + (n - 64)];
        float v2 = (n < 64) ? w_rel[k2 * 64 + n] : w_root[k2 * 64 + (n - 64)];
        unsigned h1 = f2tf32(v1), h2 = f2tf32(v2);
        sPhi[n * 68 + j] = make_uint2(h1, h2);
        sPlo[n * 68 + j] = make_uint2(f2tf32(v1 - __uint_as_float(h1)),
                                      f2tf32(v2 - __uint_as_float(h2)));
    }
    __syncthreads();
    int lane = threadIdx.x & 31, wl = threadIdx.x >> 5;
    int gID = lane >> 2, tig = lane & 3;
    int warp = blockIdx.x * 16 + wl;
    int nwarp = gridDim.x * 16;
    int ntiles = (N + 15) >> 4;
    for (int tile = warp; tile < ntiles; tile += nwarp) {
        int r_lo = tile * 16 + gID;
        int r_hi = r_lo + 8;
        const float* xlo = x + (size_t)min(r_lo, N - 1) * F_DIM;
        const float* xhi = x + (size_t)min(r_hi, N - 1) * F_DIM;
        float acc[16][4];
#pragma unroll
        for (int i = 0; i < 16; i++) {
            acc[i][0] = 0.f; acc[i][1] = 0.f; acc[i][2] = 0.f; acc[i][3] = 0.f;
        }
#pragma unroll 4
        for (int kt = 0; kt < 16; kt++) {
            int kb = kt * 8 + tig;
            float f0 = xlo[kb], f1 = xhi[kb], f2 = xlo[kb + 4], f3 = xhi[kb + 4];
            unsigned a0h = f2tf32(f0), a1h = f2tf32(f1);
            unsigned a2h = f2tf32(f2), a3h = f2tf32(f3);
            unsigned a0l = f2tf32(f0 - __uint_as_float(a0h));
            unsigned a1l = f2tf32(f1 - __uint_as_float(a1h));
            unsigned a2l = f2tf32(f2 - __uint_as_float(a2h));
            unsigned a3l = f2tf32(f3 - __uint_as_float(a3h));
#pragma unroll
            for (int nt = 0; nt < 16; nt++) {
                uint2 bh = sPhi[(nt * 8 + gID) * 68 + kt * 4 + tig];
                uint2 bl = sPlo[(nt * 8 + gID) * 68 + kt * 4 + tig];
                mma_tf32(acc[nt][0], acc[nt][1], acc[nt][2], acc[nt][3],
                         a0h, a1h, a2h, a3h, bh.x, bh.y);
                mma_tf32(acc[nt][0], acc[nt][1], acc[nt][2], acc[nt][3],
                         a0h, a1h, a2h, a3h, bl.x, bl.y);
                mma_tf32(acc[nt][0], acc[nt][1], acc[nt][2], acc[nt][3],
                         a0l, a1l, a2l, a3l, bh.x, bh.y);
            }
        }
        bool ok_lo = r_lo < N, ok_hi = r_hi < N;
#pragma unroll
        for (int nt = 0; nt < 16; nt++) {
            int col = (nt & 7) * 8 + 2 * tig;
            if (nt < 8) {
                if (ok_lo)
                    *(float2*)(d_y + (size_t)r_lo * H_DIM + col) =
                        make_float2(acc[nt][0], acc[nt][1]);
                if (ok_hi)
                    *(float2*)(d_y + (size_t)r_hi * H_DIM + col) =
                        make_float2(acc[nt][2], acc[nt][3]);
            } else {
                float bb0 = b1[col], bb1 = b1[col + 1];
                if (ok_lo)
                    *(float2*)(d_h + (size_t)r_lo * H_DIM + col) =
                        make_float2(acc[nt][0] + bb0, acc[nt][1] + bb1);
                if (ok_hi)
                    *(float2*)(d_h + (size_t)r_hi * H_DIM + col) =
                        make_float2(acc[nt][2] + bb0, acc[nt][3] + bb1);
            }
        }
    }
}

// ---------------- k_hist: (dst,rel) counts + per-block rel hist + dst counts
__global__ void k_hist(const int* __restrict__ ei, const int* __restrict__ et,
                       int E, int R, int chunk) {
    __shared__ int h[R_CAP];
    int t = threadIdx.x;
    if (t < R) h[t] = 0;
    __syncthreads();
    int s = blockIdx.x * chunk;
    int e_end = min(E, s + chunk);
    for (int e = s + t; e < e_end; e += blockDim.x) {
        int dst = ei[E + e];
        int r = et[e];
        atomicAdd(&d_cnt[(size_t)dst * R + r], 1);
        atomicAdd(&d_dcnt[dst], 1);
        atomicAdd(&h[r], 1);
    }
    __syncthreads();
    if (t < R) d_bhist[t * NBLK_B + blockIdx.x] = h[t];
}

// ---------------- k_scanall: one-kernel CSR scan ---------------
// block 0: rel-hist scan (8192 entries). blocks 1..ntiles: ticketed
// decoupled-lookback scan of d_dcnt[N] -> d_doff/d_dcur.
__global__ __launch_bounds__(256) void k_scanall(int N, int E, int R) {
    if (blockIdx.x == 0) {
        __shared__ int wsum[8];
        int t = threadIdx.x, lane = t & 31, wid = t >> 5;
        int loc[32];
        int s = 0;
        int base = t * 32;
#pragma unroll
        for (int i = 0; i < 32; i++) { loc[i] = s; s += d_bhist[base + i]; }
        int incl = s;
#pragma unroll
        for (int off = 1; off < 32; off <<= 1) {
            int v = __shfl_up_sync(0xffffffffu, incl, off);
            if (lane >= off) incl += v;
        }
        if (lane == 31) wsum[wid] = incl;
        __syncthreads();
        if (t < 8) {
            int w = wsum[t];
            for (int off = 1; off < 8; off <<= 1) {
                int v = __shfl_up_sync(0xffu, w, off);
                if (t >= off) w += v;
            }
            wsum[t] = w;
        }
        __syncthreads();
        int excl = ((wid > 0) ? wsum[wid - 1] : 0) + incl - s;
#pragma unroll
        for (int i = 0; i < 32; i++) d_boff[base + i] = excl + loc[i];
        __syncthreads();
        if (t < R) {
            int st = d_boff[t * NBLK_B];
            int en = (t + 1 < R) ? d_boff[(t + 1) * NBLK_B] : E;
            d_bstart[t] = st;
            d_bcnt[t] = en - st;
        }
        if (t == 0) d_doff[N] = E;
        return;
    }
    // ----- lookback scan tile -----
    __shared__ int wsum[8];
    __shared__ int sh[2];   // [0]=tile id, [1]=lookback base
    int t = threadIdx.x, lane = t & 31, wid = t >> 5;
    if (t == 0) sh[0] = atomicAdd(&d_ticket, 1);
    __syncthreads();
    int tile = sh[0];
    int base0 = tile * 1024 + t * 4;
    int loc[4];
    int s = 0;
#pragma unroll
    for (int i = 0; i < 4; i++) {
        int idx = base0 + i;
        int c = (idx < N) ? d_dcnt[idx] : 0;
        loc[i] = s; s += c;
    }
    int incl = s;
#pragma unroll
    for (int off = 1; off < 32; off <<= 1) {
        int v = __shfl_up_sync(0xffffffffu, incl, off);
        if (lane >= off) incl += v;
    }
    if (lane == 31) wsum[wid] = incl;
    __syncthreads();
    if (t < 8) {
        int w = wsum[t];
        for (int off = 1; off < 8; off <<= 1) {
            int v = __shfl_up_sync(0xffu, w, off);
            if (t >= off) w += v;
        }
        wsum[t] = w;
    }
    __syncthreads();
    int agg = wsum[7];
    int ebase = ((wid > 0) ? wsum[wid - 1] : 0) + incl - s;
    if (t == 0) {
        unsigned long long pk =
            ((unsigned long long)(tile == 0 ? 2 : 1) << 32) | (unsigned)agg;
        atomicExch(&d_state[tile], pk);
    }
    int tbase = 0;
    if (tile > 0) {
        if (t < 32) {
            int j = tile - 1;
            int acc = 0;
            while (true) {
                int idx = j - lane;
                int flag, val;
                do {
                    if (idx >= 0) {
                        unsigned long long st = atomicAdd(&d_state[idx], 0ULL);
                        flag = (int)(st >> 32);
                        val = (int)(st & 0xffffffffULL);
                    } else { flag = 2; val = 0; }
                } while (__any_sync(0xffffffffu, flag == 0));
                unsigned pm = __ballot_sync(0xffffffffu, flag == 2);
                int firstP = __ffs(pm) - 1;          // -1 if none
                int contrib = (firstP >= 0) ? ((lane <= firstP) ? val : 0) : val;
#pragma unroll
                for (int off = 16; off; off >>= 1)
                    contrib += __shfl_down_sync(0xffffffffu, contrib, off);
                contrib = __shfl_sync(0xffffffffu, contrib, 0);
                acc += contrib;
                if (firstP >= 0) break;
                j -= 32;
            }
            if (lane == 0) {
                sh[1] = acc;
                atomicExch(&d_state[tile], (2ULL << 32) | (unsigned)(acc + agg));
            }
        }
        __syncthreads();
        tbase = sh[1];
    }
#pragma unroll
    for (int i = 0; i < 4; i++) {
        int idx = base0 + i;
        if (idx < N) {
            int oo = tbase + ebase + loc[i];
            d_doff[idx] = oo;
            d_dcur[idx] = oo;
        }
    }
}

// ---------------- k_scatter2: BOTH scatters in one pass ---------
__global__ void k_scatter2(const int* __restrict__ ei, const int* __restrict__ et,
                           const float* __restrict__ nrm, int E, int R, int chunk) {
    __shared__ int c[R_CAP];
    int t = threadIdx.x;
    if (t < R) c[t] = d_boff[t * NBLK_B + blockIdx.x];
    __syncthreads();
    int s = blockIdx.x * chunk;
    int e_end = min(E, s + chunk);
    for (int e = s + t; e < e_end; e += blockDim.x) {
        int src = ei[e];
        int dst = ei[E + e];
        int r = et[e];
        int pos = atomicAdd(&c[r], 1);
        d_bedge[pos] = make_int2(src, dst);
        int pos2 = atomicAdd(&d_dcur[dst], 1);
        d_dedge[pos2] = make_int2(src, __float_as_int(nrm[e]));
    }
}

// ---------------- k_agg1b: warp per dst, NO atomics -------------
__global__ void k_agg1b(int N) {
    int lane = threadIdx.x & 31;
    int d = (blockIdx.x * blockDim.x + threadIdx.x) >> 5;
    if (d >= N) return;
    int s = d_doff[d], e2 = d_doff[d + 1];
    float* hp = d_h + (size_t)d * H_DIM + 2 * lane;
    float2 acc = *(float2*)hp;
    int i = s;
    for (; i + 2 <= e2; i += 2) {
        int2 a = d_dedge[i];
        int2 b = d_dedge[i + 1];
        float2 y0 = *(const float2*)(d_y + (size_t)a.x * H_DIM + 2 * lane);
        float2 y1 = *(const float2*)(d_y + (size_t)b.x * H_DIM + 2 * lane);
        float w0 = __int_as_float(a.y), w1 = __int_as_float(b.y);
        acc.x += y0.x * w0; acc.y += y0.y * w0;
        acc.x += y1.x * w1; acc.y += y1.y * w1;
    }
    if (i < e2) {
        int2 a = d_dedge[i];
        float2 y0 = *(const float2*)(d_y + (size_t)a.x * H_DIM + 2 * lane);
        float w0 = __int_as_float(a.y);
        acc.x += y0.x * w0; acc.y += y0.y * w0;
    }
    *(float2*)hp = acc;
}

// ---------------- k_oroot_mma: o = h @ w2_root + b2 (tf32 MMA) --
__global__ __launch_bounds__(256) void k_oroot_mma(
    const float* __restrict__ w2, const float* __restrict__ b2, int N) {
    __shared__ uint2 sPhi[64 * 36];
    __shared__ uint2 sPlo[64 * 36];
    for (int i = threadIdx.x; i < 64 * 32; i += 256) {
        int n = i >> 5, j = i & 31;       // j = kt*4 + tig
        int kt = j >> 2, tig = j & 3;
        int k1 = kt * 8 + tig, k2 = k1 + 4;
        float v1 = w2[k1 * 64 + n];
        float v2 = w2[k2 * 64 + n];
        unsigned h1 = f2tf32(v1), h2 = f2tf32(v2);
        sPhi[n * 36 + j] = make_uint2(h1, h2);
        sPlo[n * 36 + j] = make_uint2(f2tf32(v1 - __uint_as_float(h1)),
                                      f2tf32(v2 - __uint_as_float(h2)));
    }
    __syncthreads();
    int lane = threadIdx.x & 31, wl = threadIdx.x >> 5;
    int gID = lane >> 2, tig = lane & 3;
    int warp = blockIdx.x * 8 + wl;
    int nwarp = gridDim.x * 8;
    int ntiles = (N + 15) >> 4;
    for (int tile = warp; tile < ntiles; tile += nwarp) {
        int r_lo = tile * 16 + gID;
        int r_hi = r_lo + 8;
        const float* hlo = d_h + (size_t)min(r_lo, N - 1) * H_DIM;
        const float* hhi = d_h + (size_t)min(r_hi, N - 1) * H_DIM;
        float acc[8][4];
#pragma unroll
        for (int i = 0; i < 8; i++) {
            acc[i][0] = 0.f; acc[i][1] = 0.f; acc[i][2] = 0.f; acc[i][3] = 0.f;
        }
#pragma unroll
        for (int kt = 0; kt < 8; kt++) {
            int kb = kt * 8 + tig;
            float f0 = hlo[kb], f1 = hhi[kb], f2 = hlo[kb + 4], f3 = hhi[kb + 4];
            unsigned a0h = f2tf32(f0), a1h = f2tf32(f1);
            unsigned a2h = f2tf32(f2), a3h = f2tf32(f3);
            unsigned a0l = f2tf32(f0 - __uint_as_float(a0h));
            unsigned a1l = f2tf32(f1 - __uint_as_float(a1h));
            unsigned a2l = f2tf32(f2 - __uint_as_float(a2h));
            unsigned a3l = f2tf32(f3 - __uint_as_float(a3h));
#pragma unroll
            for (int nt = 0; nt < 8; nt++) {
                uint2 bh = sPhi[(nt * 8 + gID) * 36 + kt * 4 + tig];
                uint2 bl = sPlo[(nt * 8 + gID) * 36 + kt * 4 + tig];
                mma_tf32(acc[nt][0], acc[nt][1], acc[nt][2], acc[nt][3],
                         a0h, a1h, a2h, a3h, bh.x, bh.y);
                mma_tf32(acc[nt][0], acc[nt][1], acc[nt][2], acc[nt][3],
                         a0h, a1h, a2h, a3h, bl.x, bl.y);
                mma_tf32(acc[nt][0], acc[nt][1], acc[nt][2], acc[nt][3],
                         a0l, a1l, a2l, a3l, bh.x, bh.y);
            }
        }
        bool ok_lo = r_lo < N, ok_hi = r_hi < N;
#pragma unroll
        for (int nt = 0; nt < 8; nt++) {
            int col = nt * 8 + 2 * tig;
            float bb0 = b2[col], bb1 = b2[col + 1];
            if (ok_lo)
                *(float2*)(d_o + (size_t)r_lo * H_DIM + col) =
                    make_float2(acc[nt][0] + bb0, acc[nt][1] + bb1);
            if (ok_hi)
                *(float2*)(d_o + (size_t)r_hi * H_DIM + col) =
                    make_float2(acc[nt][2] + bb0, acc[nt][3] + bb1);
        }
    }
}

// ---------------- k_rgcn3: bucketed tf32 MMA, 16 edges/warp -----
__global__ __launch_bounds__(256) void k_rgcn3(int R) {
    __shared__ uint2 sPhi[64 * 36];
    __shared__ uint2 sPlo[64 * 36];
    int rel = blockIdx.x % R;
    int chunk = blockIdx.x / R;
    int nchunk = gridDim.x / R;
    const float* __restrict__ W = d_W + (size_t)rel * 4096;
    for (int i = threadIdx.x; i < 64 * 32; i += 256) {
        int n = i >> 5, j = i & 31;
        int kt = j >> 2, tig = j & 3;
        int k1 = kt * 8 + tig, k2 = k1 + 4;
        float v1 = W[k1 * 64 + n];
        float v2 = W[k2 * 64 + n];
        unsigned h1 = f2tf32(v1), h2 = f2tf32(v2);
        sPhi[n * 36 + j] = make_uint2(h1, h2);
        sPlo[n * 36 + j] = make_uint2(f2tf32(v1 - __uint_as_float(h1)),
                                      f2tf32(v2 - __uint_as_float(h2)));
    }
    __syncthreads();
    int start = d_bstart[rel], cnt = d_bcnt[rel];
    int lane = threadIdx.x & 31, wl = threadIdx.x >> 5;
    int gID = lane >> 2, tig = lane & 3;
    int ngroups = (cnt + 15) >> 4;
    int wstride = nchunk * 8;
    for (int g = chunk * 8 + wl; g < ngroups; g += wstride) {
        int base = start + g * 16;
        int m = min(16, cnt - g * 16);
        int2 ev = make_int2(0, 0);
        float invv = 0.f;
        if (lane < 16) {
            ev = d_bedge[base + min(lane, m - 1)];
            int c = d_cnt[(size_t)ev.y * R + rel];
            invv = 1.f / (float)(c > 1 ? c : 1);
        }
        int s_lo  = __shfl_sync(0xffffffffu, ev.x, gID);
        int s_hi  = __shfl_sync(0xffffffffu, ev.x, gID + 8);
        int d_lo  = __shfl_sync(0xffffffffu, ev.y, gID);
        int d_hi  = __shfl_sync(0xffffffffu, ev.y, gID + 8);
        float ilo = __shfl_sync(0xffffffffu, invv, gID);
        float ihi = __shfl_sync(0xffffffffu, invv, gID + 8);
        unsigned Ah[8][4], Al[8][4];
        const float* rl = d_h + (size_t)s_lo * H_DIM;
        const float* rh = d_h + (size_t)s_hi * H_DIM;
#pragma unroll
        for (int kt = 0; kt < 8; kt++) {
            float f0 = rl[kt * 8 + tig];
            float f1 = rh[kt * 8 + tig];
            float f2 = rl[kt * 8 + tig + 4];
            float f3 = rh[kt * 8 + tig + 4];
            Ah[kt][0] = f2tf32(f0); Al[kt][0] = f2tf32(f0 - __uint_as_float(Ah[kt][0]));
            Ah[kt][1] = f2tf32(f1); Al[kt][1] = f2tf32(f1 - __uint_as_float(Ah[kt][1]));
            Ah[kt][2] = f2tf32(f2); Al[kt][2] = f2tf32(f2 - __uint_as_float(Ah[kt][2]));
            Ah[kt][3] = f2tf32(f3); Al[kt][3] = f2tf32(f3 - __uint_as_float(Ah[kt][3]));
        }
#pragma unroll
        for (int nt = 0; nt < 8; nt++) {
            float c0 = 0.f, c1 = 0.f, c2 = 0.f, c3 = 0.f;
#pragma unroll
            for (int kt = 0; kt < 8; kt++) {
                uint2 bh = sPhi[(nt * 8 + gID) * 36 + kt * 4 + tig];
                uint2 bl = sPlo[(nt * 8 + gID) * 36 + kt * 4 + tig];
                mma_tf32(c0, c1, c2, c3, Ah[kt][0], Ah[kt][1], Ah[kt][2], Ah[kt][3], bh.x, bh.y);
                mma_tf32(c0, c1, c2, c3, Ah[kt][0], Ah[kt][1], Ah[kt][2], Ah[kt][3], bl.x, bl.y);
                mma_tf32(c0, c1, c2, c3, Al[kt][0], Al[kt][1], Al[kt][2], Al[kt][3], bh.x, bh.y);
            }
            int colg = nt * 8 + 2 * tig;
            if (gID < m)
                red_add_v2(d_o2 + (size_t)d_lo * H_DIM + colg, c0 * ilo, c1 * ilo);
            if (gID + 8 < m)
                red_add_v2(d_o2 + (size_t)d_hi * H_DIM + colg, c2 * ihi, c3 * ihi);
        }
    }
}

// ---------------- k_pool_x: self-computed offsets + x pooling ---
__global__ void k_pool_x(const float* __restrict__ x, const int* __restrict__ seql,
                         int G) {
    __shared__ int wsum[4];
    __shared__ int so[2];
    int g = blockIdx.x;
    int t = threadIdx.x;                 // 128 threads
    int acc = 0;
    for (int i = t; i < g; i += 128) acc += seql[i];
#pragma unroll
    for (int off = 16; off; off >>= 1) acc += __shfl_down_sync(0xffffffffu, acc, off);
    if ((t & 31) == 0) wsum[t >> 5] = acc;
    __syncthreads();
    if (t == 0) {
        int s = wsum[0] + wsum[1] + wsum[2] + wsum[3];
        so[0] = s;
        so[1] = s + seql[g];
        d_offs[g] = s;
        if (g == G - 1) d_offs[G] = s + seql[g];
    }
    __syncthreads();
    int s = so[0], e = so[1];
    float sum = 0.f, mx = -INFINITY;
#pragma unroll 4
    for (int n = s; n < e; n++) {
        float v = x[(size_t)n * F_DIM + t];
        sum += v; mx = fmaxf(mx, v);
    }
    d_pool[(size_t)g * P_DIM + t] = sum;
    d_pool[(size_t)g * P_DIM + 192 + t] = mx;
}

// ---------------- k_head2: pool(o+o2) + MLP + log_softmax -------
__global__ void k_head2(const float* __restrict__ lin_w, const float* __restrict__ lin_b,
                        const float* __restrict__ fc_w, const float* __restrict__ fc_b,
                        float* __restrict__ out, int G) {
    __shared__ float sp[P_DIM];
    __shared__ float hid[H_DIM];
    __shared__ float lg[C_DIM];
    __shared__ float lse;
    int g = blockIdx.x, t = threadIdx.x;   // 64 threads
    int s = d_offs[g], e = d_offs[g + 1];
    {
        float sum = 0.f, mx = -INFINITY;
#pragma unroll 4
        for (int n = s; n < e; n++) {
            float v = d_o[(size_t)n * H_DIM + t] + d_o2[(size_t)n * H_DIM + t];
            sum += v; mx = fmaxf(mx, v);
        }
        sp[128 + t] = sum;
        sp[320 + t] = mx;
    }
    for (int i = t; i < 128; i += 64) {
        sp[i] = d_pool[(size_t)g * P_DIM + i];
        sp[192 + i] = d_pool[(size_t)g * P_DIM + 192 + i];
    }
    __syncthreads();
    float acc = lin_b[t];
#pragma unroll 8
    for (int k = 0; k < P_DIM; k++) acc += sp[k] * lin_w[k * H_DIM + t];
    hid[t] = fmaxf(acc, 0.f);
    __syncthreads();
    if (t < C_DIM) {
        float a = fc_b[t];
#pragma unroll
        for (int k = 0; k < H_DIM; k++) a += hid[k] * fc_w[k * C_DIM + t];
        lg[t] = a;
    }
    __syncthreads();
    if (t == 0) {
        float m = -INFINITY;
        for (int j = 0; j < C_DIM; j++) m = fmaxf(m, lg[j]);
        float s2 = 0.f;
        for (int j = 0; j < C_DIM; j++) s2 += expf(lg[j] - m);
        lse = m + logf(s2);
    }
    __syncthreads();
    if (t < C_DIM) out[(size_t)g * C_DIM + t] = lg[t] - lse;
}

// ---------------- launch ----------------------------------------
extern "C" void kernel_launch(void* const* d_in, const int* in_sizes, int n_in,
                              void* d_out, int out_size) {
    int o = (n_in >= 17) ? 0 : -1;
    const float* x       = (const float*)d_in[0];
    const int*   ei      = (const int*)d_in[1];
    const float* enorm   = (const float*)d_in[2];
    const int*   etype   = (const int*)d_in[3];
    const int*   seql    = (const int*)d_in[4];
    const float* w1_rel  = (const float*)d_in[6 + o];
    const float* w1_root = (const float*)d_in[7 + o];
    const float* b1      = (const float*)d_in[8 + o];
    const float* bases   = (const float*)d_in[9 + o];
    const float* comp    = (const float*)d_in[10 + o];
    const float* w2      = (const float*)d_in[11 + o];
    const float* b2      = (const float*)d_in[12 + o];
    const float* lin_w   = (const float*)d_in[13 + o];
    const float* lin_b   = (const float*)d_in[14 + o];
    const float* fc_w    = (const float*)d_in[15 + o];
    const float* fc_b    = (const float*)d_in[16 + o];

    int N  = in_sizes[0] / F_DIM;
    int E  = in_sizes[2];
    int G  = in_sizes[4];
    int NB = in_sizes[9 + o] / (H_DIM * H_DIM);
    int R  = in_sizes[10 + o] / NB;
    float* out = (float*)d_out;
    (void)out_size;

    static cudaStream_t sA = 0, sB = 0;
    static cudaEvent_t evRoot = 0, evA = 0, evH = 0, evB2 = 0, evZ = 0;
    if (sA == 0) {
        cudaStreamCreateWithFlags(&sA, cudaStreamNonBlocking);
        cudaStreamCreateWithFlags(&sB, cudaStreamNonBlocking);
        cudaEventCreateWithFlags(&evRoot, cudaEventDisableTiming);
        cudaEventCreateWithFlags(&evA, cudaEventDisableTiming);
        cudaEventCreateWithFlags(&evH, cudaEventDisableTiming);
        cudaEventCreateWithFlags(&evB2, cudaEventDisableTiming);
        cudaEventCreateWithFlags(&evZ, cudaEventDisableTiming);
        cudaFuncSetAttribute(k_proj_mma, cudaFuncAttributeMaxDynamicSharedMemorySize,
                             128 * 68 * 8 * 2);
    }

    int chunk   = (E + NBLK_B - 1) / NBLK_B;
    int nstiles = (N + 1023) >> 10;

    // fork
    cudaEventRecord(evRoot, 0);
    cudaStreamWaitEvent(sA, evRoot, 0);
    cudaStreamWaitEvent(sB, evRoot, 0);

    // stream A: edge bucketing (independent of proj)
    k_prep<<<2048, 256, 0, sA>>>(comp, bases, R, NB, N);
    k_hist<<<NBLK_B, 256, 0, sA>>>(ei, etype, E, R, chunk);
    k_scanall<<<nstiles + 1, 256, 0, sA>>>(N, E, R);
    k_scatter2<<<NBLK_B, 256, 0, sA>>>(ei, etype, enorm, E, R, chunk);
    cudaEventRecord(evA, sA);

    // stream B: x pooling (self-computed offsets) + o2 zero
    k_pool_x<<<G, 128, 0, sB>>>(x, seql, G);
    k_zero<<<512, 256, 0, sB>>>(N);
    cudaEventRecord(evZ, sB);

    // main stream: critical path
    k_proj_mma<<<148, 512, 128 * 68 * 8 * 2>>>(x, w1_rel, w1_root, b1, N);
    cudaStreamWaitEvent(0, evA, 0);
    k_agg1b<<<(N + 7) / 8, 256>>>(N);
    cudaEventRecord(evH, 0);

    // stream B: root transform concurrent with rgcn3
    cudaStreamWaitEvent(sB, evH, 0);
    k_oroot_mma<<<296, 256, 0, sB>>>(w2, b2, N);
    cudaEventRecord(evB2, sB);

    // main: rgcn messages into d_o2 (after o2 zeroed)
    cudaStreamWaitEvent(0, evZ, 0);
    k_rgcn3<<<R * 64, 256>>>(R);
    cudaStreamWaitEvent(0, evB2, 0);
    k_head2<<<G, 64>>>(lin_w, lin_b, fc_w, fc_b, out, G);
}